// round 1
// baseline (speedup 1.0000x reference)
#include <cuda_runtime.h>
#include <math.h>

#define NUSER 100000
#define NITEM 50000
#define NENT  200000
#define NREL  32
#define D     64
#define NEDGE 500000
#define NNZ   2000000
#define NUI   (NUSER + NITEM)

// ---------------- scratch (device globals; no allocation allowed) ----------
__device__ float g_ent [NENT * D];   // current entity embeddings (hop input)
__device__ float g_sums[NENT * D];   // segment sums
__device__ float g_res [NENT * D];   // residual accumulator ent_res
__device__ float g_cnt [NENT];       // segment counts
__device__ float g_bufA[NUI * D];    // GCN ping
__device__ float g_bufB[NUI * D];    // GCN pong

// ---------------- helpers ----------------
__device__ __forceinline__ float wredsum(float v) {
    v += __shfl_xor_sync(0xffffffffu, v, 16);
    v += __shfl_xor_sync(0xffffffffu, v, 8);
    v += __shfl_xor_sync(0xffffffffu, v, 4);
    v += __shfl_xor_sync(0xffffffffu, v, 2);
    v += __shfl_xor_sync(0xffffffffu, v, 1);
    return v;
}

__device__ __forceinline__ void red2(float* p, float a, float b) {
#if __CUDA_ARCH__ >= 900
    atomicAdd(reinterpret_cast<float2*>(p), make_float2(a, b));
#else
    atomicAdd(p, a); atomicAdd(p + 1, b);
#endif
}

// ---------------- RGAT edge kernel: one warp per edge ----------------
__global__ void k_rgat(const float* __restrict__ ent, const float* __restrict__ rel,
                       const int* __restrict__ head, const int* __restrict__ tail,
                       const int* __restrict__ etype,
                       float* __restrict__ sums, float* __restrict__ cnt)
{
    int wid  = (blockIdx.x * blockDim.x + threadIdx.x) >> 5;
    int lane = threadIdx.x & 31;
    if (wid >= NEDGE) return;

    int h = head[wid];
    int t = tail[wid];
    int r = etype[wid] - 1;

    const float2* e2 = reinterpret_cast<const float2*>(ent);
    const float2* r2 = reinterpret_cast<const float2*>(rel);
    float2 he = e2[(size_t)h * 32 + lane];
    float2 te = e2[(size_t)t * 32 + lane];
    float2 re = r2[(size_t)r * 32 + lane];

    const float MINN = 1e-15f;

    // ---- batch reductions, pass 1 ----
    float trx = te.x + re.x, tryy = te.y + re.y;
    float s_tere = wredsum(trx * trx + tryy * tryy);            // ||te+re||^2
    float s_he   = wredsum(he.x * he.x + he.y * he.y);          // ||he||^2
    float s_te   = wredsum(te.x * te.x + te.y * te.y);          // ||te||^2
    float s_re   = wredsum(re.x * re.x + re.y * re.y);          // ||re||^2
    float d_het  = wredsum(he.x * te.x + he.y * te.y);          // dot(he,te)
    float d_her  = wredsum(he.x * re.x + he.y * re.y);          // dot(he,re)

    // hh = expmap0(he) = tanh(n)/n * he ; alpha scaling keeps dots cheap
    float n_he  = fmaxf(sqrtf(s_he), MINN);
    float alpha = tanhf(n_he) / n_he;
    float hhx = alpha * he.x, hhy = alpha * he.y;
    float sq_hh = alpha * alpha * s_he;
    float one_m_hh = fmaxf(1.0f - sq_hh, MINN);  // = 2/lam
    float lam = 2.0f / one_m_hh;

    // ht = expmap(te, hh) = mobius_add(hh, a*te),  a = tanh(0.5*lam*||te||)/||te||
    float n_te = fmaxf(sqrtf(s_te), MINN);
    float a_t = tanhf(0.5f * lam * n_te) / n_te;
    float y2t = a_t * a_t * s_te;
    float xyt = a_t * alpha * d_het;
    float ct1 = 1.0f + 2.0f * xyt + y2t;
    float ct2 = 1.0f - sq_hh;
    float dent = fmaxf(1.0f + 2.0f * xyt + sq_hh * y2t, MINN);
    float htx = (ct1 * hhx + ct2 * (a_t * te.x)) / dent;
    float hty = (ct1 * hhy + ct2 * (a_t * te.y)) / dent;

    // hr = expmap(re, hh)
    float n_re = fmaxf(sqrtf(s_re), MINN);
    float a_r = tanhf(0.5f * lam * n_re) / n_re;
    float y2r = a_r * a_r * s_re;
    float xyr = a_r * alpha * d_her;
    float cr1 = 1.0f + 2.0f * xyr + y2r;
    float denr = fmaxf(1.0f + 2.0f * xyr + sq_hh * y2r, MINN);
    float hrx = (cr1 * hhx + ct2 * (a_r * re.x)) / denr;
    float hry = (cr1 * hhy + ct2 * (a_r * re.y)) / denr;

    // ---- reductions, pass 2 ----
    float s_ht   = wredsum(htx * htx + hty * hty);
    float s_hr   = wredsum(hrx * hrx + hry * hry);
    float d_hthr = wredsum(htx * hrx + hty * hry);

    // m = mobius_add(ht, hr)
    float cm1 = 1.0f + 2.0f * d_hthr + s_hr;
    float cm2 = 1.0f - s_ht;
    float denm = fmaxf(1.0f + 2.0f * d_hthr + s_ht * s_hr, MINN);
    float mx = (cm1 * htx + cm2 * hrx) / denm;
    float my = (cm1 * hty + cm2 * hry) / denm;

    // project to ball
    float s_m = wredsum(mx * mx + my * my);
    float n_m = fmaxf(sqrtf(s_m), MINN);
    const float MAXN = 1.0f - 1e-3f;
    float scale = (n_m > MAXN) ? (MAXN / n_m) : 1.0f;
    float rx = mx * scale, ry = my * scale;
    float sq_res = s_m * scale * scale;

    // logmap(res, hh): sub = mobius_add(-hh, res)
    float d_hres = wredsum(hhx * rx + hhy * ry);
    float xy = -d_hres;
    float cl1 = 1.0f + 2.0f * xy + sq_res;
    float denl = fmaxf(1.0f + 2.0f * xy + sq_hh * sq_res, MINN);
    float subx = (cl1 * (-hhx) + ct2 * rx) / denl;
    float suby = (cl1 * (-hhy) + ct2 * ry) / denl;

    float s_sub = wredsum(subx * subx + suby * suby);
    float n_sub = fmaxf(sqrtf(s_sub), MINN);
    float coef = one_m_hh * atanhf(fminf(n_sub, 1.0f - 1e-5f)) / n_sub;

    // ricci = l2norm(te+re)
    float inv_tere = 1.0f / fmaxf(sqrtf(s_tere), 1e-12f);

    float ox = coef * subx + trx * inv_tere * 1e-7f;
    float oy = coef * suby + tryy * inv_tere * 1e-7f;
    ox = fmaxf(ox, 0.0f);
    oy = fmaxf(oy, 0.0f);

    red2(sums + (size_t)h * D + 2 * lane, ox, oy);
    if (lane == 0) atomicAdd(cnt + h, 1.0f);
}

// ---------------- mean + l2norm + residual: one warp per entity row --------
__global__ void k_post(const float* __restrict__ sums, const float* __restrict__ cnt,
                       float* __restrict__ ent, float* __restrict__ res)
{
    int wid  = (blockIdx.x * blockDim.x + threadIdx.x) >> 5;
    int lane = threadIdx.x & 31;
    if (wid >= NENT) return;

    float c = fmaxf(cnt[wid], 1.0f);
    float2 v = reinterpret_cast<const float2*>(sums)[(size_t)wid * 32 + lane];
    v.x /= c; v.y /= c;
    float s = wredsum(v.x * v.x + v.y * v.y);
    float inv = 1.0f / fmaxf(sqrtf(s), 1e-12f);
    v.x *= inv; v.y *= inv;
    reinterpret_cast<float2*>(ent)[(size_t)wid * 32 + lane] = v;
    float2 o = reinterpret_cast<float2*>(res)[(size_t)wid * 32 + lane];
    o.x = 0.5f * o.x + v.x;
    o.y = 0.5f * o.y + v.y;
    reinterpret_cast<float2*>(res)[(size_t)wid * 32 + lane] = o;
}

// ---------------- build concat embeds into cur and out ---------------------
__global__ void k_embeds(const float* __restrict__ u, const float* __restrict__ res,
                         float* __restrict__ cur, float* __restrict__ out)
{
    int i = blockIdx.x * blockDim.x + threadIdx.x;  // float2 index
    if (i >= NUI * 32) return;
    int row = i >> 5;
    float2 v;
    if (row < NUSER) v = reinterpret_cast<const float2*>(u)[i];
    else             v = reinterpret_cast<const float2*>(res)[i - NUSER * 32];
    reinterpret_cast<float2*>(cur)[i] = v;
    reinterpret_cast<float2*>(out)[i] = v;
}

// ---------------- COO SpMM: one warp per nnz -------------------------------
__global__ void k_spmm(const float* __restrict__ val, const int* __restrict__ row,
                       const int* __restrict__ col,
                       const float* __restrict__ cur, float* __restrict__ nxt)
{
    int wid  = (blockIdx.x * blockDim.x + threadIdx.x) >> 5;
    int lane = threadIdx.x & 31;
    if (wid >= NNZ) return;
    int rr = row[wid];
    int cc = col[wid];
    float v = val[wid];
    float2 x = reinterpret_cast<const float2*>(cur)[(size_t)cc * 32 + lane];
    red2(nxt + (size_t)rr * D + 2 * lane, v * x.x, v * x.y);
}

// ---------------- out += a -------------------------------------------------
__global__ void k_add(const float* __restrict__ a, float* __restrict__ out)
{
    int i = blockIdx.x * blockDim.x + threadIdx.x;  // float2 index
    if (i >= NUI * 32) return;
    float2 av = reinterpret_cast<const float2*>(a)[i];
    float2 ov = reinterpret_cast<float2*>(out)[i];
    ov.x += av.x; ov.y += av.y;
    reinterpret_cast<float2*>(out)[i] = ov;
}

// ---------------- launch ---------------------------------------------------
extern "C" void kernel_launch(void* const* d_in, const int* in_sizes, int n_in,
                              void* d_out, int out_size)
{
    const float* uE   = (const float*)d_in[0];
    const float* eE   = (const float*)d_in[1];
    const float* rE   = (const float*)d_in[2];
    const float* aval = (const float*)d_in[3];
    const int*   eh   = (const int*)d_in[4];
    const int*   et   = (const int*)d_in[5];
    const int*   ety  = (const int*)d_in[6];
    const int*   arow = (const int*)d_in[7];
    const int*   acol = (const int*)d_in[8];
    float* out = (float*)d_out;

    float *ent, *sums, *res, *cnt, *A, *B;
    cudaGetSymbolAddress((void**)&ent,  g_ent);
    cudaGetSymbolAddress((void**)&sums, g_sums);
    cudaGetSymbolAddress((void**)&res,  g_res);
    cudaGetSymbolAddress((void**)&cnt,  g_cnt);
    cudaGetSymbolAddress((void**)&A,    g_bufA);
    cudaGetSymbolAddress((void**)&B,    g_bufB);

    const size_t entBytes = (size_t)NENT * D * sizeof(float);
    const size_t uiBytes  = (size_t)NUI  * D * sizeof(float);

    cudaMemcpyAsync(ent, eE, entBytes, cudaMemcpyDeviceToDevice);
    cudaMemcpyAsync(res, eE, entBytes, cudaMemcpyDeviceToDevice);

    for (int hop = 0; hop < 2; hop++) {
        cudaMemsetAsync(sums, 0, entBytes);
        cudaMemsetAsync(cnt,  0, (size_t)NENT * sizeof(float));
        k_rgat<<<(NEDGE + 7) / 8, 256>>>(ent, rE, eh, et, ety, sums, cnt);
        k_post<<<(NENT + 7) / 8, 256>>>(sums, cnt, ent, res);
    }

    // embeds = concat(uEmbeds, ent_res[:NITEM]); total = embeds
    k_embeds<<<(NUI * 32 + 255) / 256, 256>>>(uE, res, A, out);

    // GCN layer 1: B = spmm(adj, A); total += B
    cudaMemsetAsync(B, 0, uiBytes);
    k_spmm<<<(NNZ + 7) / 8, 256>>>(aval, arow, acol, A, B);
    k_add<<<(NUI * 32 + 255) / 256, 256>>>(B, out);

    // GCN layer 2: A = spmm(adj, B); total += A
    cudaMemsetAsync(A, 0, uiBytes);
    k_spmm<<<(NNZ + 7) / 8, 256>>>(aval, arow, acol, B, A);
    k_add<<<(NUI * 32 + 255) / 256, 256>>>(A, out);
}

// round 2
// speedup vs baseline: 2.1463x; 2.1463x over previous
#include <cuda_runtime.h>
#include <math.h>

#define NUSER 100000
#define NITEM 50000
#define NENT  200000
#define NREL  32
#define D     64
#define NEDGE 500000
#define NNZ   2000000
#define NUI   (NUSER + NITEM)
#define FULL  0xffffffffu

// ---------------- scratch (device globals; no runtime allocation) ----------
__device__ float g_sA[NENT * D];    // hop1 sums -> ent1 (in-place post)
__device__ float g_sB[NENT * D];    // hop2 sums -> ent2
__device__ float g_cnt[NENT];
__device__ float g_A[NUI * D];      // embeds
__device__ float g_B[NUI * D];      // gcn intermediate
__device__ int   g_acnt[NUI];
__device__ int   g_aptr[NUI + 1];
__device__ int   g_acur[NUI];
__device__ int   g_acol[NNZ];
__device__ float g_aval[NNZ];
__device__ int   g_bsums[1024];

// ---------------- helpers ----------------
__device__ __forceinline__ float wredsum(float v) {
    v += __shfl_xor_sync(FULL, v, 16);
    v += __shfl_xor_sync(FULL, v, 8);
    v += __shfl_xor_sync(FULL, v, 4);
    v += __shfl_xor_sync(FULL, v, 2);
    v += __shfl_xor_sync(FULL, v, 1);
    return v;
}
// 16-lane (half-warp) reduction
__device__ __forceinline__ float hredsum(float v) {
    v += __shfl_xor_sync(FULL, v, 8);
    v += __shfl_xor_sync(FULL, v, 4);
    v += __shfl_xor_sync(FULL, v, 2);
    v += __shfl_xor_sync(FULL, v, 1);
    return v;
}
__device__ __forceinline__ void red2(float* p, float a, float b) {
    atomicAdd(reinterpret_cast<float2*>(p), make_float2(a, b));
}
__device__ __forceinline__ float dot4(float4 a, float4 b) {
    return a.x * b.x + a.y * b.y + a.z * b.z + a.w * b.w;
}
__device__ __forceinline__ float tanhf_fast(float x) {  // x >= 0
    if (x < 1e-4f) return x;
    float e = __expf(2.0f * x);
    return __fdividef(e - 1.0f, e + 1.0f);
}
__device__ __forceinline__ float atanhf_fast(float x) { // 0 <= x <= 1-1e-5
    return 0.5f * __logf(__fdividef(1.0f + x, 1.0f - x));
}

// ---------------- RGAT: 2 edges per warp (16-lane halves, float4) ----------
__global__ void __launch_bounds__(256) k_rgat(
    const float* __restrict__ entP, const float* __restrict__ rel,
    const int* __restrict__ head, const int* __restrict__ tail,
    const int* __restrict__ etype,
    float* __restrict__ sums, float* __restrict__ cnt)
{
    __shared__ float s_rel[NREL * D];
    for (int i = threadIdx.x; i < NREL * D; i += blockDim.x) s_rel[i] = rel[i];
    __syncthreads();

    int lane = threadIdx.x & 31;
    int half = lane >> 4;
    int sl   = lane & 15;
    int e = ((blockIdx.x * blockDim.x + threadIdx.x) >> 5) * 2 + half;
    // NEDGE is even and grid covers exactly NEDGE/2 warps: no tail.

    int h = head[e];
    int t = tail[e];
    int r = etype[e] - 1;

    const float4* e4 = reinterpret_cast<const float4*>(entP);
    float4 he = e4[(size_t)h * 16 + sl];
    float4 te = e4[(size_t)t * 16 + sl];
    float4 re = reinterpret_cast<const float4*>(s_rel)[r * 16 + sl];

    // 6 base reductions (one parallel pass)
    float A = hredsum(dot4(he, he));
    float B = hredsum(dot4(te, te));
    float C = hredsum(dot4(re, re));
    float P = hredsum(dot4(he, te));
    float Q = hredsum(dot4(he, re));
    float R = hredsum(dot4(te, re));

    const float MINN = 1e-15f;
    // hh = expmap0(he) = alpha * he
    float nhe   = fmaxf(sqrtf(A), MINN);
    float alpha = __fdividef(tanhf_fast(nhe), nhe);
    float sq    = alpha * alpha * A;        // ||hh||^2
    float omq   = 1.0f - sq;                // (1 - x2), unclamped uses
    float lamden = fmaxf(omq, MINN);        // 2/lam
    float lam   = __fdividef(2.0f, lamden);
    // ht = expmap(te, hh) = p1*he + p2*te
    float nte = fmaxf(sqrtf(B), MINN);
    float at  = __fdividef(tanhf_fast(0.5f * lam * nte), nte);
    float y2t = at * at * B;
    float xyt = at * alpha * P;
    float dent = fmaxf(1.0f + 2.0f * xyt + sq * y2t, MINN);
    float p1 = __fdividef((1.0f + 2.0f * xyt + y2t) * alpha, dent);
    float p2 = __fdividef(omq * at, dent);
    // hr = expmap(re, hh) = q1*he + q3*re
    float nre = fmaxf(sqrtf(C), MINN);
    float ar  = __fdividef(tanhf_fast(0.5f * lam * nre), nre);
    float y2r = ar * ar * C;
    float xyr = ar * alpha * Q;
    float denr = fmaxf(1.0f + 2.0f * xyr + sq * y2r, MINN);
    float q1 = __fdividef((1.0f + 2.0f * xyr + y2r) * alpha, denr);
    float q3 = __fdividef(omq * ar, denr);
    // scalar dots of ht, hr
    float sht = p1 * p1 * A + 2.0f * p1 * p2 * P + p2 * p2 * B;
    float shr = q1 * q1 * A + 2.0f * q1 * q3 * Q + q3 * q3 * C;
    float dhh = p1 * q1 * A + p1 * q3 * Q + p2 * q1 * P + p2 * q3 * R;
    // m = mobius_add(ht, hr) = m1*he + m2*te + m3*re
    float denm = fmaxf(1.0f + 2.0f * dhh + sht * shr, MINN);
    float f1 = __fdividef(1.0f + 2.0f * dhh + shr, denm);
    float f2 = __fdividef(1.0f - sht, denm);
    float m1 = f1 * p1 + f2 * q1;
    float m2 = f1 * p2;
    float m3 = f2 * q3;
    float sm = m1 * m1 * A + m2 * m2 * B + m3 * m3 * C
             + 2.0f * (m1 * m2 * P + m1 * m3 * Q + m2 * m3 * R);
    sm = fmaxf(sm, 0.0f);
    // project
    float nm = fmaxf(sqrtf(sm), MINN);
    float scale = (nm > 0.999f) ? __fdividef(0.999f, nm) : 1.0f;
    float sqres = sm * scale * scale;
    // logmap(res, hh): sub = u1*he + u2*te + u3*re
    float dhres = scale * alpha * (m1 * A + m2 * P + m3 * Q);
    float xy = -dhres;
    float denl = fmaxf(1.0f + 2.0f * xy + sq * sqres, MINN);
    float gg1 = __fdividef(1.0f + 2.0f * xy + sqres, denl);
    float gg2 = __fdividef(omq, denl);
    float u1 = -gg1 * alpha + gg2 * scale * m1;
    float u2 = gg2 * scale * m2;
    float u3 = gg2 * scale * m3;
    float ssub = u1 * u1 * A + u2 * u2 * B + u3 * u3 * C
               + 2.0f * (u1 * u2 * P + u1 * u3 * Q + u2 * u3 * R);
    ssub = fmaxf(ssub, 0.0f);
    float nsub = fmaxf(sqrtf(ssub), MINN);
    float coef = lamden * __fdividef(atanhf_fast(fminf(nsub, 1.0f - 1e-5f)), nsub);
    // ricci coefficient
    float stere = B + 2.0f * R + C;
    float epst = __fdividef(1e-7f, fmaxf(sqrtf(stere), 1e-12f));

    float c1 = coef * u1;
    float c2 = coef * u2 + epst;
    float c3 = coef * u3 + epst;

    float ox = fmaxf(c1 * he.x + c2 * te.x + c3 * re.x, 0.0f);
    float oy = fmaxf(c1 * he.y + c2 * te.y + c3 * re.y, 0.0f);
    float oz = fmaxf(c1 * he.z + c2 * te.z + c3 * re.z, 0.0f);
    float ow = fmaxf(c1 * he.w + c2 * te.w + c3 * re.w, 0.0f);

    float* base = sums + (size_t)h * D + sl * 4;
    red2(base, ox, oy);
    red2(base + 2, oz, ow);
    if (sl == 0) atomicAdd(cnt + h, 1.0f);
}

// ---------------- mean + l2norm, in place; one warp per entity -------------
__global__ void __launch_bounds__(256) k_post(float* __restrict__ buf,
                                              const float* __restrict__ cnt)
{
    int w = (blockIdx.x * blockDim.x + threadIdx.x) >> 5;
    int lane = threadIdx.x & 31;
    float ic = __fdividef(1.0f, fmaxf(cnt[w], 1.0f));
    float2* b2 = reinterpret_cast<float2*>(buf);
    float2 v = b2[(size_t)w * 32 + lane];
    v.x *= ic; v.y *= ic;
    float s = wredsum(v.x * v.x + v.y * v.y);
    float inv = __fdividef(1.0f, fmaxf(sqrtf(s), 1e-12f));
    v.x *= inv; v.y *= inv;
    b2[(size_t)w * 32 + lane] = v;
}

// ---------------- embeds = concat(u, 0.25*e0 + 0.5*n1 + n2) ----------------
__global__ void __launch_bounds__(256) k_embeds(
    const float* __restrict__ u, const float* __restrict__ e0,
    const float* __restrict__ n1, const float* __restrict__ n2,
    float* __restrict__ Aout, float* __restrict__ out)
{
    int i = blockIdx.x * blockDim.x + threadIdx.x;  // float2 index, exact grid
    int row = i >> 5;
    float2 v;
    if (row < NUSER) {
        v = reinterpret_cast<const float2*>(u)[i];
    } else {
        int j = i - NUSER * 32;
        float2 a = reinterpret_cast<const float2*>(e0)[j];
        float2 b = reinterpret_cast<const float2*>(n1)[j];
        float2 c = reinterpret_cast<const float2*>(n2)[j];
        v.x = 0.25f * a.x + 0.5f * b.x + c.x;
        v.y = 0.25f * a.y + 0.5f * b.y + c.y;
    }
    reinterpret_cast<float2*>(Aout)[i] = v;
    reinterpret_cast<float2*>(out)[i] = v;
}

// ---------------- adj CSR build --------------------------------------------
__global__ void k_ahist(const int* __restrict__ row, int* __restrict__ cnt) {
    int i = blockIdx.x * blockDim.x + threadIdx.x;
    if (i < NNZ) atomicAdd(&cnt[row[i]], 1);
}
__global__ void k_blocksum(const int* __restrict__ cnt, int n, int* __restrict__ bs) {
    __shared__ int sh[1024];
    int i = blockIdx.x * 1024 + threadIdx.x;
    sh[threadIdx.x] = (i < n) ? cnt[i] : 0;
    __syncthreads();
    for (int s = 512; s > 0; s >>= 1) {
        if (threadIdx.x < s) sh[threadIdx.x] += sh[threadIdx.x + s];
        __syncthreads();
    }
    if (threadIdx.x == 0) bs[blockIdx.x] = sh[0];
}
__global__ void k_scanbsums(int* __restrict__ bs, int nb) {
    __shared__ int sh[1024];
    int v = (threadIdx.x < nb) ? bs[threadIdx.x] : 0;
    sh[threadIdx.x] = v;
    __syncthreads();
    for (int off = 1; off < 1024; off <<= 1) {
        int t = (threadIdx.x >= off) ? sh[threadIdx.x - off] : 0;
        __syncthreads();
        sh[threadIdx.x] += t;
        __syncthreads();
    }
    if (threadIdx.x < nb) bs[threadIdx.x] = sh[threadIdx.x] - v;  // exclusive
}
__global__ void k_scanblock(const int* __restrict__ cnt, int n,
                            const int* __restrict__ bs,
                            int* __restrict__ ptr, int* __restrict__ cur) {
    __shared__ int sh[1024];
    int i = blockIdx.x * 1024 + threadIdx.x;
    int v = (i < n) ? cnt[i] : 0;
    sh[threadIdx.x] = v;
    __syncthreads();
    for (int off = 1; off < 1024; off <<= 1) {
        int t = (threadIdx.x >= off) ? sh[threadIdx.x - off] : 0;
        __syncthreads();
        sh[threadIdx.x] += t;
        __syncthreads();
    }
    int excl = sh[threadIdx.x] - v + bs[blockIdx.x];
    if (i < n) { ptr[i] = excl; cur[i] = excl; }
    if (i == n - 1) ptr[n] = excl + v;
}
__global__ void k_ascatter(const int* __restrict__ row, const int* __restrict__ col,
                           const float* __restrict__ val,
                           int* __restrict__ cur,
                           int* __restrict__ ocol, float* __restrict__ oval) {
    int i = blockIdx.x * blockDim.x + threadIdx.x;
    if (i >= NNZ) return;
    int pos = atomicAdd(&cur[row[i]], 1);
    ocol[pos] = col[i];
    oval[pos] = val[i];
}

// ---------------- CSR SpMM: warp per row, no atomics, fused out += ---------
template <int STORE>
__global__ void __launch_bounds__(256) k_spmm(
    const float* __restrict__ curbuf, const int* __restrict__ ptr,
    const int* __restrict__ cols, const float* __restrict__ vals,
    float* __restrict__ nxt, float* __restrict__ out)
{
    int w = (blockIdx.x * blockDim.x + threadIdx.x) >> 5;
    int lane = threadIdx.x & 31;
    int beg = ptr[w], end = ptr[w + 1];
    const float2* c2 = reinterpret_cast<const float2*>(curbuf);
    float2 acc = make_float2(0.0f, 0.0f);
    for (int base = beg; base < end; base += 32) {
        int i = base + lane;
        int c = 0; float v = 0.0f;
        if (i < end) { c = cols[i]; v = vals[i]; }
        int n = min(end - base, 32);
        for (int j = 0; j < n; j++) {
            int cc = __shfl_sync(FULL, c, j);
            float vv = __shfl_sync(FULL, v, j);
            float2 x = c2[(size_t)cc * 32 + lane];
            acc.x = fmaf(vv, x.x, acc.x);
            acc.y = fmaf(vv, x.y, acc.y);
        }
    }
    size_t o = (size_t)w * 32 + lane;
    if (STORE) reinterpret_cast<float2*>(nxt)[o] = acc;
    float2 ov = reinterpret_cast<float2*>(out)[o];
    ov.x += acc.x; ov.y += acc.y;
    reinterpret_cast<float2*>(out)[o] = ov;
}

// ---------------- launch ---------------------------------------------------
extern "C" void kernel_launch(void* const* d_in, const int* in_sizes, int n_in,
                              void* d_out, int out_size)
{
    const float* uE   = (const float*)d_in[0];
    const float* eE   = (const float*)d_in[1];
    const float* rE   = (const float*)d_in[2];
    const float* aval = (const float*)d_in[3];
    const int*   eh   = (const int*)d_in[4];
    const int*   et   = (const int*)d_in[5];
    const int*   ety  = (const int*)d_in[6];
    const int*   arow = (const int*)d_in[7];
    const int*   acol = (const int*)d_in[8];
    float* out = (float*)d_out;

    float *sA, *sB, *cnt, *A, *B, *avalS;
    int *acnt, *aptr, *acur, *acolS, *bsums;
    cudaGetSymbolAddress((void**)&sA,    g_sA);
    cudaGetSymbolAddress((void**)&sB,    g_sB);
    cudaGetSymbolAddress((void**)&cnt,   g_cnt);
    cudaGetSymbolAddress((void**)&A,     g_A);
    cudaGetSymbolAddress((void**)&B,     g_B);
    cudaGetSymbolAddress((void**)&acnt,  g_acnt);
    cudaGetSymbolAddress((void**)&aptr,  g_aptr);
    cudaGetSymbolAddress((void**)&acur,  g_acur);
    cudaGetSymbolAddress((void**)&acolS, g_acol);
    cudaGetSymbolAddress((void**)&avalS, g_aval);
    cudaGetSymbolAddress((void**)&bsums, g_bsums);

    const size_t entBytes = (size_t)NENT * D * sizeof(float);
    const int nbA = (NUI + 1023) / 1024;  // 147

    // ---- adj CSR build (also overlaps conceptually with nothing; it's fast)
    cudaMemsetAsync(acnt, 0, NUI * sizeof(int));
    k_ahist<<<(NNZ + 255) / 256, 256>>>(arow, acnt);
    k_blocksum<<<nbA, 1024>>>(acnt, NUI, bsums);
    k_scanbsums<<<1, 1024>>>(bsums, nbA);
    k_scanblock<<<nbA, 1024>>>(acnt, NUI, bsums, aptr, acur);
    k_ascatter<<<(NNZ + 255) / 256, 256>>>(arow, acol, aval, acur, acolS, avalS);

    // ---- RGAT hop 1 (input = eE directly)
    cudaMemsetAsync(sA, 0, entBytes);
    cudaMemsetAsync(cnt, 0, NENT * sizeof(float));
    k_rgat<<<NEDGE / 16, 256>>>(eE, rE, eh, et, ety, sA, cnt);
    k_post<<<NENT / 8, 256>>>(sA, cnt);

    // ---- RGAT hop 2
    cudaMemsetAsync(sB, 0, entBytes);
    cudaMemsetAsync(cnt, 0, NENT * sizeof(float));
    k_rgat<<<NEDGE / 16, 256>>>(sA, rE, eh, et, ety, sB, cnt);
    k_post<<<NENT / 8, 256>>>(sB, cnt);

    // ---- embeds + total init (ent_res = 0.25*e0 + 0.5*n1 + n2)
    k_embeds<<<NUI * 32 / 256, 256>>>(uE, eE, sA, sB, A, out);

    // ---- GCN layers via CSR, out += fused
    k_spmm<1><<<NUI / 8, 256>>>(A, aptr, acolS, avalS, B, out);
    k_spmm<0><<<NUI / 8, 256>>>(B, aptr, acolS, avalS, nullptr, out);
}